// round 15
// baseline (speedup 1.0000x reference)
#include <cuda_runtime.h>
#include <cuda_bf16.h>
#include <cstdint>

// ============================================================
// Problem dims
// ============================================================
#define VOCAB   32000
#define HID     256
#define BATCH   16
#define TLEN    256
#define NROWS   (BATCH * TLEN)     // 4096
#define NVS     16                 // vocab splits
#define VSPLIT  (VOCAB / NVS)      // 2000
#define CHUNK   80                 // vocab rows per pipeline chunk
#define NCHUNK  (VSPLIT / CHUNK)   // 25
#define NTILES  32                 // (pair, quarter) tiles of 128 rows
#define NTASKS  (NTILES * NVS)     // 512
#define NRNN    32                 // 2 CTAs (one cluster) per batch
#define NWORKER 112
#define GRID    (NRNN + NWORKER)   // 144 CTAs, single wave, even (cluster=2)

// ============================================================
// Device scratch (static — no runtime allocation)
// ============================================================
__device__ __nv_bfloat16 g_Wfc_bf16[(size_t)VOCAB * HID];   // 16.4 MB
__device__ __nv_bfloat16 g_hs[(size_t)NROWS * HID];         // 2 MB
__device__ float g_partials[NVS * NROWS];
__device__ float g_tlogit[NROWS];
__device__ int   g_tile_ready[NTILES];   // counts to 4 (2 batches x 2 ranks)
__device__ int   g_ticket;

// ============================================================
// PTX helpers (target-neutral: sm_90-base instructions only)
// ============================================================
__device__ __forceinline__ uint32_t smem_to_u32(const void* p) {
    uint32_t a;
    asm("{ .reg .u64 t; cvta.to.shared.u64 t, %1; cvt.u32.u64 %0, t; }" : "=r"(a) : "l"(p));
    return a;
}

__device__ __forceinline__ void cp16(uint32_t smem_dst, const void* gsrc) {
    asm volatile("cp.async.cg.shared.global [%0], [%1], 16;"
                 :: "r"(smem_dst), "l"(gsrc) : "memory");
}
__device__ __forceinline__ void cp_commit() {
    asm volatile("cp.async.commit_group;" ::: "memory");
}
template <int N>
__device__ __forceinline__ void cp_wait() {
    asm volatile("cp.async.wait_group %0;" :: "n"(N) : "memory");
}

__device__ __forceinline__ void ldsm4(uint32_t* r, uint32_t addr) {
    asm volatile("ldmatrix.sync.aligned.m8n8.x4.shared.b16 {%0,%1,%2,%3}, [%4];"
                 : "=r"(r[0]), "=r"(r[1]), "=r"(r[2]), "=r"(r[3]) : "r"(addr));
}

__device__ __forceinline__ void mma16816(float* c, const uint32_t* a, uint32_t b0, uint32_t b1) {
    asm volatile(
        "mma.sync.aligned.m16n8k16.row.col.f32.bf16.bf16.f32 "
        "{%0,%1,%2,%3}, {%4,%5,%6,%7}, {%8,%9}, {%0,%1,%2,%3};"
        : "+f"(c[0]), "+f"(c[1]), "+f"(c[2]), "+f"(c[3])
        : "r"(a[0]), "r"(a[1]), "r"(a[2]), "r"(a[3]), "r"(b0), "r"(b1));
}

// ---- cluster / DSMEM / mbarrier (sm_90 base) ----
__device__ __forceinline__ uint32_t cluster_rank() {
    uint32_t r; asm("mov.u32 %0, %%cluster_ctarank;" : "=r"(r)); return r;
}
__device__ __forceinline__ uint32_t mapa_peer(uint32_t saddr, uint32_t peer) {
    uint32_t r;
    asm("mapa.shared::cluster.u32 %0, %1, %2;" : "=r"(r) : "r"(saddr), "r"(peer));
    return r;
}
__device__ __forceinline__ void st_cluster_f32(uint32_t addr, float v) {
    asm volatile("st.shared::cluster.f32 [%0], %1;" :: "r"(addr), "f"(v) : "memory");
}
#define CLUSTER_ARRIVE() asm volatile("barrier.cluster.arrive.aligned;" ::: "memory")
#define CLUSTER_WAIT()   asm volatile("barrier.cluster.wait.aligned;"   ::: "memory")

#define MBARRIER_INIT(addr, count) \
    asm volatile("mbarrier.init.shared.b64 [%0], %1;" \
                 :: "r"((uint32_t)(addr)), "r"((uint32_t)(count)) : "memory")

// arrive on an mbarrier in a peer CTA's SMEM (release at cluster scope)
#define MBARRIER_ARRIVE_REMOTE(remAddr) \
    asm volatile("mbarrier.arrive.shared::cluster.b64 _, [%0];" \
                 :: "r"((uint32_t)(remAddr)) : "memory")

// wait on a local mbarrier with cluster-scope acquire (sees peer DSMEM stores)
#define MBAR_WAIT_CLUSTER(mbar_addr, phase_parity) do { \
    uint32_t _mbar = (uint32_t)(mbar_addr); \
    uint32_t _parity = (uint32_t)(phase_parity); \
    uint32_t _done; \
    asm volatile( \
        "{\n\t.reg .pred p;\n\t" \
        "mbarrier.try_wait.parity.acquire.cluster.shared::cta.b64 p, [%1], %2;\n\t" \
        "selp.b32 %0, 1, 0, p;\n\t}" \
        : "=r"(_done) : "r"(_mbar), "r"(_parity) : "memory"); \
    if (!_done) { \
        asm volatile( \
            "{\n\t.reg .pred P1;\n\t" \
            "WAIT_LOOP_%=:\n\t" \
            "mbarrier.try_wait.parity.acquire.cluster.shared::cta.b64 P1, [%0], %1, 0x989680;\n\t" \
            "@P1 bra.uni WAIT_DONE_%=;\n\t" \
            "bra.uni WAIT_LOOP_%=;\n\t" \
            "WAIT_DONE_%=:\n\t}" \
            :: "r"(_mbar), "r"(_parity) : "memory"); \
    } \
} while (0)

// ============================================================
// Kernel 1: Wfc fp32 -> bf16, plus per-replay reset of flags/ticket
// ============================================================
__global__ void __launch_bounds__(256) convert_wfc_kernel(const float* __restrict__ Wfc) {
    if (blockIdx.x == 0) {
        if (threadIdx.x < NTILES) g_tile_ready[threadIdx.x] = 0;
        if (threadIdx.x == NTILES) g_ticket = 0;
    }
    int idx = blockIdx.x * blockDim.x + threadIdx.x;   // over 2,048,000 float4s
    const float4* src = (const float4*)Wfc;
    float4 v = src[idx];
    __nv_bfloat162* dst = (__nv_bfloat162*)g_Wfc_bf16;
    dst[2 * idx + 0] = __floats2bfloat162_rn(v.x, v.y);
    dst[2 * idx + 1] = __floats2bfloat162_rn(v.z, v.w);
}

// ============================================================
// Fused kernel SMEM layout (worker role), bytes:
//   A   : [0, 67584)         128 rows x 528
//   B0  : [67584, 109824)    80 rows x 528
//   B1  : [109824, 152064)
//   bfc0: [152064, 152384)   80 f32
//   bfc1: [152384, 152704)
//   task: [152704, 152708)
// RNN role reuses: hbuf 2x256 f32 [0,2048), toks 256 i32 [2048,3072),
//                  mbar ring 2x8B [3584,3600)
// ============================================================
#define AST   528
#define BST   528
#define SM_A    0
#define SM_B0   67584
#define SM_B1   109824
#define SM_F0   152064
#define SM_F1   152384
#define SM_TASK 152704
#define SM_TOT  152768

#define SM_RNN_MBAR 3584

// ---------------- RNN role: one 2-CTA cluster per batch ----------------
// CTA rank r owns hidden rows [128r, 128r+128). Thread tid: row = tid>>1
// (global ge = 128r + row), k-sub s = tid&1. Thread holds TWO 64-wide weight
// windows in registers: own-half k in [128r + 64s, +64) and peer-half k in
// [128(r^1) + 64s, +64).
//
// Per-step schedule (hides DSMEM transit):
//   1. dot over OWN window (h local, ready since last bar)
//   2. mbarrier wait for peer exchange t-1 (usually already satisfied —
//      the transit overlapped step t-1's tail + our own-window dot)
//   3. dot over PEER window
//   4. combine partner lanes via shfl_xor(1) — no SMEM, no extra bar
//   5. s==0 lane: tanh, store h local + DSMEM to peer, g_hs, arrive on
//      peer's mbar ring
//   6. one __syncthreads (local h visibility + slot reuse)
// Overwrite safety: slot written at exchange t is rewritten at exchange t+2,
// gated on the reader's exchange t+1 arrive, which postdates its reads.
__device__ __forceinline__ void rnn_role(
    char* smc, const int* __restrict__ inputs, const float* __restrict__ Wih,
    const float* __restrict__ bih, const float* __restrict__ Whh,
    const float* __restrict__ bhh)
{
    float* hbuf = (float*)smc;               // 2 x 256 (ping-pong)
    int*   toks = (int*)(smc + 2048);        // 256
    const uint32_t smb = smem_to_u32(smc);
    const uint32_t mbar = smb + SM_RNN_MBAR; // 2 x 8B ring

    const int b = blockIdx.x >> 1;
    const uint32_t rank = cluster_rank();
    const uint32_t peer_hbuf = mapa_peer(smb, rank ^ 1);
    const uint32_t peer_mbar = mapa_peer(mbar, rank ^ 1);
    const int tid = threadIdx.x;
    const int row = tid >> 1;                // 0..127
    const int s   = tid & 1;                 // k-sub within each half
    const int ge  = (int)rank * 128 + row;
    const int k_own  = (int)rank * 128 + s * 64;
    const int k_peer = ((int)rank ^ 1) * 128 + s * 64;

    toks[tid] = inputs[b * TLEN + tid];

    // Two 64-wide weight windows in registers (128 f32 total)
    float w_own[64], w_peer[64];
    {
        const float4* wo = (const float4*)(Whh + (size_t)ge * 256 + k_own);
        const float4* wp = (const float4*)(Whh + (size_t)ge * 256 + k_peer);
#pragma unroll
        for (int k = 0; k < 16; k++) {
            float4 v = wo[k];
            w_own[4 * k] = v.x; w_own[4 * k + 1] = v.y;
            w_own[4 * k + 2] = v.z; w_own[4 * k + 3] = v.w;
            float4 u = wp[k];
            w_peer[4 * k] = u.x; w_peer[4 * k + 1] = u.y;
            w_peer[4 * k + 2] = u.z; w_peer[4 * k + 3] = u.w;
        }
    }
    const float bsum = bih[ge] + bhh[ge];
    hbuf[tid] = 0.f; hbuf[256 + tid] = 0.f;
    if (tid == 0) {
        MBARRIER_INIT(mbar + 0, 128);
        MBARRIER_INIT(mbar + 8, 128);
    }
    __syncthreads();
    CLUSTER_ARRIVE(); CLUSTER_WAIT();        // peer hbuf + mbars initialized

    int cur = 0;
    for (int t = 0; t < TLEN; t++) {
        const float* hp = hbuf + cur * 256;
        const int tok = toks[t];
        float x = __ldg(Wih + (size_t)tok * 256 + ge);   // L2-latency hidden under dot

        // ---- own-window dot (local data) ----
        float a0 = 0.f, a1 = 0.f;
        {
            const float* hpo = hp + k_own;
#pragma unroll
            for (int k = 0; k < 64; k += 8) {
                float4 h0 = *(const float4*)(hpo + k);
                float4 h1 = *(const float4*)(hpo + k + 4);
                a0 += w_own[k]     * h0.x + w_own[k + 1] * h0.y;
                a1 += w_own[k + 2] * h0.z + w_own[k + 3] * h0.w;
                a0 += w_own[k + 4] * h1.x + w_own[k + 5] * h1.y;
                a1 += w_own[k + 6] * h1.z + w_own[k + 7] * h1.w;
            }
        }

        // ---- wait for peer exchange t-1 (transit hidden under own dot) ----
        if (t > 0) {
            const int ex = t - 1;
            MBAR_WAIT_CLUSTER(mbar + (ex & 1) * 8, (ex >> 1) & 1);
        }

        // ---- peer-window dot ----
        float b0 = 0.f, b1 = 0.f;
        {
            const float* hpp = hp + k_peer;
#pragma unroll
            for (int k = 0; k < 64; k += 8) {
                float4 h0 = *(const float4*)(hpp + k);
                float4 h1 = *(const float4*)(hpp + k + 4);
                b0 += w_peer[k]     * h0.x + w_peer[k + 1] * h0.y;
                b1 += w_peer[k + 2] * h0.z + w_peer[k + 3] * h0.w;
                b0 += w_peer[k + 4] * h1.x + w_peer[k + 5] * h1.y;
                b1 += w_peer[k + 6] * h1.z + w_peer[k + 7] * h1.w;
            }
        }

        float d = (a0 + a1) + (b0 + b1);
        d += __shfl_xor_sync(0xFFFFFFFFu, d, 1);          // partner lane (same warp)

        if (s == 0) {
            float h = tanhf(x + bsum + d);
            const int slot = (cur ^ 1) * 256 + ge;
            hbuf[slot] = h;                                   // own copy
            st_cluster_f32(peer_hbuf + slot * 4, h);          // peer copy (DSMEM)
            g_hs[((size_t)b * TLEN + t) * 256 + ge] = __float2bfloat16(h);
            if ((t & 63) == 63) __threadfence();              // publish g_hs
            MBARRIER_ARRIVE_REMOTE(peer_mbar + (t & 1) * 8);  // signal exchange t
        }
        __syncthreads();                      // local h slot visible; slot reuse safe
        if (tid == 0 && (t & 63) == 63)
            atomicAdd(&g_tile_ready[(t >> 6) * 8 + (b >> 1)], 1);
        cur ^= 1;
    }
    CLUSTER_ARRIVE(); CLUSTER_WAIT();        // drain in-flight DSMEM before exit
}

// ---------------- GEMM worker role ----------------
__device__ __forceinline__ void load_chunk(char* smc, uint32_t smb, int tid,
                                           int v0, int c, int buf,
                                           const float* __restrict__ bfc)
{
    const char* src = (const char*)(g_Wfc_bf16 + (size_t)(v0 + c * CHUNK) * HID);
    uint32_t dstB = smb + (buf ? SM_B1 : SM_B0);
#pragma unroll
    for (int it = 0; it < 10; it++) {
        int i = it * 256 + tid;               // 2560 x 16B
        int row = i >> 5, cc = i & 31;
        cp16(dstB + row * BST + cc * 16, src + row * 512 + cc * 16);
    }
    if (tid < 20)
        cp16(smb + (buf ? SM_F1 : SM_F0) + tid * 16,
             (const char*)(bfc + v0 + c * CHUNK) + tid * 16);
}

__device__ __forceinline__ void worker_role(
    char* smc, const int* __restrict__ targets, const float* __restrict__ bfc)
{
    const uint32_t smb = smem_to_u32(smc);
    const int tid = threadIdx.x;
    const int w = tid >> 5;
    const int lid = tid & 31;
    int* s_task = (int*)(smc + SM_TASK);

    // ldmatrix A base: warp owns 16 rows (one m-tile)
    const uint32_t aaddr = smb + SM_A + (w * 16 + (lid & 15)) * AST + (lid >> 4) * 16;
    // ldmatrix B base (x4 = 2 n-tiles)
    const uint32_t boff = (((lid >> 4) << 3) + (lid & 7)) * BST + ((lid >> 3) & 1) * 16;

    for (;;) {
        if (tid == 0) *s_task = atomicAdd(&g_ticket, 1);
        __syncthreads();
        const int task = *s_task;
        if (task >= NTASKS) break;

        const int tt = task >> 4;                   // tile id, quarter-major
        const int vs = task & 15;
        const int q  = tt >> 3;                     // t-quarter 0..3
        const int pr = tt & 7;                      // batch pair 0..7
        const int v0 = vs * VSPLIT;

        // prefetch B chunks 0,1 while waiting for the tile
        load_chunk(smc, smb, tid, v0, 0, 0, bfc); cp_commit();
        load_chunk(smc, smb, tid, v0, 1, 1, bfc); cp_commit();

        if (tid == 0)
            while (atomicAdd(&g_tile_ready[tt], 0) < 4) __nanosleep(256);
        __syncthreads();
        __threadfence();   // acquire: hs stores visible before we read them

        // A tile: rows 0-63 = batch 2*pr, rows 64-127 = batch 2*pr+1,
        // timesteps [q*64, q*64+64). 128 rows x 256 K bf16 -> SMEM stride 528.
        {
            const uint4* a0src = (const uint4*)(g_hs + ((size_t)(2 * pr) * 256 + q * 64) * HID);
            const uint4* a1src = (const uint4*)(g_hs + ((size_t)(2 * pr + 1) * 256 + q * 64) * HID);
#pragma unroll
            for (int it = 0; it < 8; it++) {
                int i = it * 256 + tid;               // 2048 x 16B per half
                int row = i >> 5, cc = i & 31;
                *(uint4*)(smc + SM_A + row * AST + cc * 16) = a0src[i];
                *(uint4*)(smc + SM_A + (row + 64) * AST + cc * 16) = a1src[i];
            }
        }

        // warp row base (global row index)
        const int rb = (2 * pr + (w >> 2)) * 256 + q * 64 + (w & 3) * 16;
        int tg[2]; float tl[2] = {0.f, 0.f}; float sums[2] = {0.f, 0.f};
        tg[0] = targets[rb + (lid >> 2)];
        tg[1] = targets[rb + 8 + (lid >> 2)];

        __syncthreads();   // A tile visible

        for (int c = 0; c < NCHUNK; c++) {
            const int buf = c & 1;
            cp_wait<1>();        // one group committed per iter -> chunk c resident
            __syncthreads();

            float acc[10][4];
#pragma unroll
            for (int nt = 0; nt < 10; nt++)
#pragma unroll
                for (int qq = 0; qq < 4; qq++) acc[nt][qq] = 0.f;

            const uint32_t bbase = smb + (buf ? SM_B1 : SM_B0) + boff;

#pragma unroll
            for (int ks = 0; ks < 16; ks++) {
                uint32_t a0[4];
                ldsm4(a0, aaddr + ks * 32);
                uint32_t bfr[5][4];
#pragma unroll
                for (int p = 0; p < 5; p++)
                    ldsm4(bfr[p], bbase + p * 16 * BST + ks * 32);
#pragma unroll
                for (int nt = 0; nt < 10; nt++)
                    mma16816(acc[nt], a0, bfr[nt >> 1][(nt & 1) * 2], bfr[nt >> 1][(nt & 1) * 2 + 1]);
            }

            // epilogue: add bfc, exp-accumulate, capture target logit
            const float* fb = (const float*)(smc + (buf ? SM_F1 : SM_F0));
            const int vbase = v0 + c * CHUNK + 2 * (lid & 3);
#pragma unroll
            for (int nt = 0; nt < 10; nt++) {
                float2 f2 = *(const float2*)(fb + nt * 8 + 2 * (lid & 3));
                const int v = vbase + nt * 8;
                float l0 = acc[nt][0] + f2.x;
                float l1 = acc[nt][1] + f2.y;
                float l2 = acc[nt][2] + f2.x;
                float l3 = acc[nt][3] + f2.y;
                sums[0] += __expf(l0) + __expf(l1);
                sums[1] += __expf(l2) + __expf(l3);
                if (v     == tg[0]) tl[0] = l0;
                if (v + 1 == tg[0]) tl[0] = l1;
                if (v     == tg[1]) tl[1] = l2;
                if (v + 1 == tg[1]) tl[1] = l3;
            }

            __syncthreads();   // buf reads done before refill
            if (c + 2 < NCHUNK) load_chunk(smc, smb, tid, v0, c + 2, buf, bfc);
            cp_commit();       // unconditional: keeps wait_group accounting exact
        }

        // reduce across quad lanes, store per-task partials
#pragma unroll
        for (int s = 0; s < 2; s++) {
            float v = sums[s];
            v += __shfl_xor_sync(0xFFFFFFFFu, v, 1);
            v += __shfl_xor_sync(0xFFFFFFFFu, v, 2);
            float t = tl[s];
            t += __shfl_xor_sync(0xFFFFFFFFu, t, 1);
            t += __shfl_xor_sync(0xFFFFFFFFu, t, 2);
            if ((lid & 3) == 0) {
                int r = rb + s * 8 + (lid >> 2);
                g_partials[vs * NROWS + r] = v;
                if ((unsigned)(tg[s] - v0) < (unsigned)VSPLIT) g_tlogit[r] = t;
            }
        }
        __syncthreads();   // partial writes / A reuse ordering before next task
    }
}

// ---------------- fused kernel ----------------
__global__ void __launch_bounds__(256, 1) __cluster_dims__(2, 1, 1)
fused_kernel(const int* __restrict__ inputs, const int* __restrict__ targets,
             const float* __restrict__ Wih, const float* __restrict__ bih,
             const float* __restrict__ Whh, const float* __restrict__ bhh,
             const float* __restrict__ bfc)
{
    extern __shared__ char smc[];
    if (blockIdx.x < NRNN)
        rnn_role(smc, inputs, Wih, bih, Whh, bhh);
    else
        worker_role(smc, targets, bfc);
}

// ============================================================
// Finalize: loss = mean_r [ log(sum_vs partial[vs][r]) - tlogit[r] ]
// ============================================================
__global__ void __launch_bounds__(1024, 1) finalize_kernel(float* __restrict__ out)
{
    __shared__ float red[1024];
    const int tid = threadIdx.x;
    float local = 0.f;
#pragma unroll
    for (int rr = 0; rr < 4; rr++) {
        int r = rr * 1024 + tid;
        float se = 0.f;
#pragma unroll
        for (int s = 0; s < NVS; s++)
            se += g_partials[s * NROWS + r];
        local += logf(se) - g_tlogit[r];
    }
    red[tid] = local;
    __syncthreads();
    for (int o = 512; o > 0; o >>= 1) {
        if (tid < o) red[tid] += red[tid + o];
        __syncthreads();
    }
    if (tid == 0) out[0] = red[0] * (1.0f / NROWS);
}

// ============================================================
// Launch
// ============================================================
extern "C" void kernel_launch(void* const* d_in, const int* in_sizes, int n_in,
                              void* d_out, int out_size)
{
    const int*   inputs  = (const int*)d_in[0];
    const int*   targets = (const int*)d_in[1];
    const float* Wih     = (const float*)d_in[2];
    const float* bih     = (const float*)d_in[3];
    const float* Whh     = (const float*)d_in[4];
    const float* bhh     = (const float*)d_in[5];
    const float* Wfc     = (const float*)d_in[6];
    const float* bfc     = (const float*)d_in[7];

    cudaFuncSetAttribute(fused_kernel, cudaFuncAttributeMaxDynamicSharedMemorySize, SM_TOT);

    convert_wfc_kernel<<<(VOCAB * HID / 4) / 256, 256>>>(Wfc);
    fused_kernel<<<GRID, 256, SM_TOT>>>(inputs, targets, Wih, bih, Whh, bhh, bfc);
    finalize_kernel<<<1, 1024>>>((float*)d_out);
}

// round 16
// speedup vs baseline: 1.6630x; 1.6630x over previous
#include <cuda_runtime.h>
#include <cuda_bf16.h>
#include <cstdint>

// ============================================================
// Problem dims
// ============================================================
#define VOCAB   32000
#define HID     256
#define BATCH   16
#define TLEN    256
#define NROWS   (BATCH * TLEN)     // 4096
#define NVS     16                 // vocab splits
#define VSPLIT  (VOCAB / NVS)      // 2000
#define CHUNK   80                 // vocab rows per pipeline chunk
#define NCHUNK  (VSPLIT / CHUNK)   // 25
#define NTILES  32                 // (eighth, batch-quad) tiles of 128 rows
#define NTASKS  (NTILES * NVS)     // 512
#define NRNN    32                 // 2 CTAs (one cluster) per batch
#define NWORKER 112
#define GRID    (NRNN + NWORKER)   // 144 CTAs, single wave, even (cluster=2)

// ============================================================
// Device scratch (static — no runtime allocation)
// ============================================================
__device__ __nv_bfloat16 g_Wfc_bf16[(size_t)VOCAB * HID];   // 16.4 MB
__device__ __nv_bfloat16 g_hs[(size_t)NROWS * HID];         // 2 MB
__device__ float g_partials[NVS * NROWS];
__device__ float g_tlogit[NROWS];
__device__ int   g_tile_ready[NTILES];   // counts to 8 (4 batches x 2 ranks)
__device__ int   g_ticket;

// ============================================================
// PTX helpers (target-neutral: sm_90-base instructions only)
// ============================================================
__device__ __forceinline__ uint32_t smem_to_u32(const void* p) {
    uint32_t a;
    asm("{ .reg .u64 t; cvta.to.shared.u64 t, %1; cvt.u32.u64 %0, t; }" : "=r"(a) : "l"(p));
    return a;
}

__device__ __forceinline__ void cp16(uint32_t smem_dst, const void* gsrc) {
    asm volatile("cp.async.cg.shared.global [%0], [%1], 16;"
                 :: "r"(smem_dst), "l"(gsrc) : "memory");
}
__device__ __forceinline__ void cp_commit() {
    asm volatile("cp.async.commit_group;" ::: "memory");
}
template <int N>
__device__ __forceinline__ void cp_wait() {
    asm volatile("cp.async.wait_group %0;" :: "n"(N) : "memory");
}

__device__ __forceinline__ void ldsm4(uint32_t* r, uint32_t addr) {
    asm volatile("ldmatrix.sync.aligned.m8n8.x4.shared.b16 {%0,%1,%2,%3}, [%4];"
                 : "=r"(r[0]), "=r"(r[1]), "=r"(r[2]), "=r"(r[3]) : "r"(addr));
}

__device__ __forceinline__ void mma16816(float* c, const uint32_t* a, uint32_t b0, uint32_t b1) {
    asm volatile(
        "mma.sync.aligned.m16n8k16.row.col.f32.bf16.bf16.f32 "
        "{%0,%1,%2,%3}, {%4,%5,%6,%7}, {%8,%9}, {%0,%1,%2,%3};"
        : "+f"(c[0]), "+f"(c[1]), "+f"(c[2]), "+f"(c[3])
        : "r"(a[0]), "r"(a[1]), "r"(a[2]), "r"(a[3]), "r"(b0), "r"(b1));
}

// ---- cluster / DSMEM / mbarrier (sm_90 base) ----
__device__ __forceinline__ uint32_t cluster_rank() {
    uint32_t r; asm("mov.u32 %0, %%cluster_ctarank;" : "=r"(r)); return r;
}
__device__ __forceinline__ uint32_t mapa_peer(uint32_t saddr, uint32_t peer) {
    uint32_t r;
    asm("mapa.shared::cluster.u32 %0, %1, %2;" : "=r"(r) : "r"(saddr), "r"(peer));
    return r;
}
__device__ __forceinline__ void st_cluster_f32(uint32_t addr, float v) {
    asm volatile("st.shared::cluster.f32 [%0], %1;" :: "r"(addr), "f"(v) : "memory");
}
#define CLUSTER_ARRIVE() asm volatile("barrier.cluster.arrive.aligned;" ::: "memory")
#define CLUSTER_WAIT()   asm volatile("barrier.cluster.wait.aligned;"   ::: "memory")

#define MBARRIER_INIT(addr, count) \
    asm volatile("mbarrier.init.shared.b64 [%0], %1;" \
                 :: "r"((uint32_t)(addr)), "r"((uint32_t)(count)) : "memory")

// arrive on an mbarrier in a peer CTA's SMEM (release at cluster scope)
#define MBARRIER_ARRIVE_REMOTE(remAddr) \
    asm volatile("mbarrier.arrive.shared::cluster.b64 _, [%0];" \
                 :: "r"((uint32_t)(remAddr)) : "memory")

// wait on a local mbarrier with cluster-scope acquire (sees peer DSMEM stores)
#define MBAR_WAIT_CLUSTER(mbar_addr, phase_parity) do { \
    uint32_t _mbar = (uint32_t)(mbar_addr); \
    uint32_t _parity = (uint32_t)(phase_parity); \
    uint32_t _done; \
    asm volatile( \
        "{\n\t.reg .pred p;\n\t" \
        "mbarrier.try_wait.parity.acquire.cluster.shared::cta.b64 p, [%1], %2;\n\t" \
        "selp.b32 %0, 1, 0, p;\n\t}" \
        : "=r"(_done) : "r"(_mbar), "r"(_parity) : "memory"); \
    if (!_done) { \
        asm volatile( \
            "{\n\t.reg .pred P1;\n\t" \
            "WAIT_LOOP_%=:\n\t" \
            "mbarrier.try_wait.parity.acquire.cluster.shared::cta.b64 P1, [%0], %1, 0x989680;\n\t" \
            "@P1 bra.uni WAIT_DONE_%=;\n\t" \
            "bra.uni WAIT_LOOP_%=;\n\t" \
            "WAIT_DONE_%=:\n\t}" \
            :: "r"(_mbar), "r"(_parity) : "memory"); \
    } \
} while (0)

// ============================================================
// Kernel 1: Wfc fp32 -> bf16, plus per-replay reset of flags/ticket
// ============================================================
__global__ void __launch_bounds__(256) convert_wfc_kernel(const float* __restrict__ Wfc) {
    if (blockIdx.x == 0) {
        if (threadIdx.x < NTILES) g_tile_ready[threadIdx.x] = 0;
        if (threadIdx.x == NTILES) g_ticket = 0;
    }
    int idx = blockIdx.x * blockDim.x + threadIdx.x;   // over 2,048,000 float4s
    const float4* src = (const float4*)Wfc;
    float4 v = src[idx];
    __nv_bfloat162* dst = (__nv_bfloat162*)g_Wfc_bf16;
    dst[2 * idx + 0] = __floats2bfloat162_rn(v.x, v.y);
    dst[2 * idx + 1] = __floats2bfloat162_rn(v.z, v.w);
}

// ============================================================
// Fused kernel SMEM layout (worker role), bytes:
//   A   : [0, 67584)         128 rows x 528
//   B0  : [67584, 109824)    80 rows x 528
//   B1  : [109824, 152064)
//   bfc0: [152064, 152384)   80 f32
//   bfc1: [152384, 152704)
//   task: [152704, 152708)
// RNN role reuses: hbuf 2x256 f32 [0,2048), part 128 f32 [2048,2560),
//                  toks 256 i32 [2560,3584), mbar ring 2x8B [3584,3600)
// ============================================================
#define AST   528
#define BST   528
#define SM_A    0
#define SM_B0   67584
#define SM_B1   109824
#define SM_F0   152064
#define SM_F1   152384
#define SM_TASK 152704
#define SM_TOT  152768

#define SM_RNN_MBAR 3584

// ---------------- RNN role: one 2-CTA cluster per batch ----------------
// IDENTICAL to the 377us R13 kernel except the readiness publish is now at
// every 32 steps (eighth granularity): flag[(t>>5)*4 + (b>>2)], counts to 8.
__device__ __forceinline__ void rnn_role(
    char* smc, const int* __restrict__ inputs, const float* __restrict__ Wih,
    const float* __restrict__ bih, const float* __restrict__ Whh,
    const float* __restrict__ bhh)
{
    float* hbuf = (float*)smc;               // 2 x 256 (ping-pong)
    float* part = (float*)(smc + 2048);      // 128
    int*   toks = (int*)(smc + 2560);        // 256
    const uint32_t smb = smem_to_u32(smc);
    const uint32_t mbar = smb + SM_RNN_MBAR; // 2 x 8B ring

    const int b = blockIdx.x >> 1;
    const uint32_t rank = cluster_rank();
    const uint32_t peer_hbuf = mapa_peer(smb, rank ^ 1);
    const uint32_t peer_mbar = mapa_peer(mbar, rank ^ 1);
    const int tid = threadIdx.x;
    const int e  = tid & 127;
    const int kh = tid >> 7;
    const int ge = (int)rank * 128 + e;
    const bool needs_wait = (kh != (int)rank);   // this thread reads the peer half

    toks[tid] = inputs[b * TLEN + tid];

    // 128 weights in registers: row ge, cols [128kh, 128kh+128)
    float w[128];
    {
        const float4* wr = (const float4*)(Whh + (size_t)ge * 256 + kh * 128);
#pragma unroll
        for (int k = 0; k < 32; k++) {
            float4 v = wr[k];
            w[4 * k] = v.x; w[4 * k + 1] = v.y; w[4 * k + 2] = v.z; w[4 * k + 3] = v.w;
        }
    }
    const float bsum = (kh == 0) ? (bih[ge] + bhh[ge]) : 0.f;
    hbuf[tid] = 0.f; hbuf[256 + tid] = 0.f;
    if (tid == 0) {
        MBARRIER_INIT(mbar + 0, 128);
        MBARRIER_INIT(mbar + 8, 128);
    }
    __syncthreads();
    CLUSTER_ARRIVE(); CLUSTER_WAIT();        // peer hbuf + mbars initialized

    int cur = 0;
    for (int t = 0; t < TLEN; t++) {
        const float* hp = hbuf + cur * 256 + kh * 128;
        const int tok = toks[t];
        float x = 0.f;
        if (kh == 0) x = __ldg(Wih + (size_t)tok * 256 + ge);   // issue before wait

        if (needs_wait && t > 0) {
            const int ex = t - 1;
            MBAR_WAIT_CLUSTER(mbar + (ex & 1) * 8, (ex >> 1) & 1);
        }

        float a0 = 0.f, a1 = 0.f, a2 = 0.f, a3 = 0.f;
#pragma unroll
        for (int k = 0; k < 128; k += 8) {
            float4 h0 = *(const float4*)(hp + k);
            float4 h1 = *(const float4*)(hp + k + 4);
            a0 += w[k]     * h0.x + w[k + 1] * h0.y;
            a1 += w[k + 2] * h0.z + w[k + 3] * h0.w;
            a2 += w[k + 4] * h1.x + w[k + 5] * h1.y;
            a3 += w[k + 6] * h1.z + w[k + 7] * h1.w;
        }
        float dot = (a0 + a1) + (a2 + a3);

        if (kh) part[e] = dot;
        __syncthreads();                      // part visible; all hbuf[cur] reads done
        if (!kh) {
            float h = tanhf(x + bsum + dot + part[e]);
            const int slot = (cur ^ 1) * 256 + ge;
            hbuf[slot] = h;                                   // own copy
            st_cluster_f32(peer_hbuf + slot * 4, h);          // peer copy (DSMEM)
            g_hs[((size_t)b * TLEN + t) * 256 + ge] = __float2bfloat16(h);
            if ((t & 31) == 31) __threadfence();              // publish g_hs
            MBARRIER_ARRIVE_REMOTE(peer_mbar + (t & 1) * 8);  // signal exchange t
        }
        __syncthreads();                      // local hbuf slot visible to own warps
        if (tid == 0 && (t & 31) == 31)
            atomicAdd(&g_tile_ready[(t >> 5) * 4 + (b >> 2)], 1);
        cur ^= 1;
    }
    CLUSTER_ARRIVE(); CLUSTER_WAIT();        // drain in-flight DSMEM before exit
}

// ---------------- GEMM worker role ----------------
__device__ __forceinline__ void load_chunk(char* smc, uint32_t smb, int tid,
                                           int v0, int c, int buf,
                                           const float* __restrict__ bfc)
{
    const char* src = (const char*)(g_Wfc_bf16 + (size_t)(v0 + c * CHUNK) * HID);
    uint32_t dstB = smb + (buf ? SM_B1 : SM_B0);
#pragma unroll
    for (int it = 0; it < 10; it++) {
        int i = it * 256 + tid;               // 2560 x 16B
        int row = i >> 5, cc = i & 31;
        cp16(dstB + row * BST + cc * 16, src + row * 512 + cc * 16);
    }
    if (tid < 20)
        cp16(smb + (buf ? SM_F1 : SM_F0) + tid * 16,
             (const char*)(bfc + v0 + c * CHUNK) + tid * 16);
}

__device__ __forceinline__ void worker_role(
    char* smc, const int* __restrict__ targets, const float* __restrict__ bfc)
{
    const uint32_t smb = smem_to_u32(smc);
    const int tid = threadIdx.x;
    const int w = tid >> 5;
    const int lid = tid & 31;
    int* s_task = (int*)(smc + SM_TASK);

    // ldmatrix A base: warp owns 16 rows (one m-tile)
    const uint32_t aaddr = smb + SM_A + (w * 16 + (lid & 15)) * AST + (lid >> 4) * 16;
    // ldmatrix B base (x4 = 2 n-tiles)
    const uint32_t boff = (((lid >> 4) << 3) + (lid & 7)) * BST + ((lid >> 3) & 1) * 16;

    for (;;) {
        if (tid == 0) *s_task = atomicAdd(&g_ticket, 1);
        __syncthreads();
        const int task = *s_task;
        if (task >= NTASKS) break;

        const int tt = task >> 4;                   // tile id, eighth-major
        const int vs = task & 15;
        const int eh = tt >> 2;                     // t-eighth 0..7
        const int qd = tt & 3;                      // batch quad 0..3
        const int v0 = vs * VSPLIT;
        const int e32 = eh * 32;

        // prefetch B chunks 0,1 while waiting for the tile
        load_chunk(smc, smb, tid, v0, 0, 0, bfc); cp_commit();
        load_chunk(smc, smb, tid, v0, 1, 1, bfc); cp_commit();

        if (tid == 0)
            while (atomicAdd(&g_tile_ready[tt], 0) < 8) __nanosleep(256);
        __syncthreads();
        __threadfence();   // acquire: hs stores visible before we read them

        // A tile: 4 strips of 32 rows — row_local rl: batch 4*qd + (rl>>5),
        // timestep e32 + (rl&31). 128 rows x 256 K bf16 -> SMEM stride 528.
        {
            const uint4* hsrc = (const uint4*)g_hs;   // 32 uint4 per row
#pragma unroll
            for (int it = 0; it < 16; it++) {
                int i = it * 256 + tid;               // 4096 x 16B
                int rl = i >> 5, cc = i & 31;
                int gr = (4 * qd + (rl >> 5)) * 256 + e32 + (rl & 31);
                *(uint4*)(smc + SM_A + rl * AST + cc * 16) = hsrc[(size_t)gr * 32 + cc];
            }
        }

        // warp row base (global row index): warp w covers rl in [16w,16w+16)
        const int rb = (4 * qd + (w >> 1)) * 256 + e32 + (w & 1) * 16;
        int tg[2]; float tl[2] = {0.f, 0.f}; float sums[2] = {0.f, 0.f};
        tg[0] = targets[rb + (lid >> 2)];
        tg[1] = targets[rb + 8 + (lid >> 2)];

        __syncthreads();   // A tile visible

        for (int c = 0; c < NCHUNK; c++) {
            const int buf = c & 1;
            cp_wait<1>();        // one group committed per iter -> chunk c resident
            __syncthreads();

            float acc[10][4];
#pragma unroll
            for (int nt = 0; nt < 10; nt++)
#pragma unroll
                for (int qq = 0; qq < 4; qq++) acc[nt][qq] = 0.f;

            const uint32_t bbase = smb + (buf ? SM_B1 : SM_B0) + boff;

#pragma unroll
            for (int ks = 0; ks < 16; ks++) {
                uint32_t a0[4];
                ldsm4(a0, aaddr + ks * 32);
                uint32_t bfr[5][4];
#pragma unroll
                for (int p = 0; p < 5; p++)
                    ldsm4(bfr[p], bbase + p * 16 * BST + ks * 32);
#pragma unroll
                for (int nt = 0; nt < 10; nt++)
                    mma16816(acc[nt], a0, bfr[nt >> 1][(nt & 1) * 2], bfr[nt >> 1][(nt & 1) * 2 + 1]);
            }

            // epilogue: add bfc, exp-accumulate, capture target logit
            const float* fb = (const float*)(smc + (buf ? SM_F1 : SM_F0));
            const int vbase = v0 + c * CHUNK + 2 * (lid & 3);
#pragma unroll
            for (int nt = 0; nt < 10; nt++) {
                float2 f2 = *(const float2*)(fb + nt * 8 + 2 * (lid & 3));
                const int v = vbase + nt * 8;
                float l0 = acc[nt][0] + f2.x;
                float l1 = acc[nt][1] + f2.y;
                float l2 = acc[nt][2] + f2.x;
                float l3 = acc[nt][3] + f2.y;
                sums[0] += __expf(l0) + __expf(l1);
                sums[1] += __expf(l2) + __expf(l3);
                if (v     == tg[0]) tl[0] = l0;
                if (v + 1 == tg[0]) tl[0] = l1;
                if (v     == tg[1]) tl[1] = l2;
                if (v + 1 == tg[1]) tl[1] = l3;
            }

            __syncthreads();   // buf reads done before refill
            if (c + 2 < NCHUNK) load_chunk(smc, smb, tid, v0, c + 2, buf, bfc);
            cp_commit();       // unconditional: keeps wait_group accounting exact
        }

        // reduce across quad lanes, store per-task partials
#pragma unroll
        for (int s = 0; s < 2; s++) {
            float v = sums[s];
            v += __shfl_xor_sync(0xFFFFFFFFu, v, 1);
            v += __shfl_xor_sync(0xFFFFFFFFu, v, 2);
            float t = tl[s];
            t += __shfl_xor_sync(0xFFFFFFFFu, t, 1);
            t += __shfl_xor_sync(0xFFFFFFFFu, t, 2);
            if ((lid & 3) == 0) {
                int r = rb + s * 8 + (lid >> 2);
                g_partials[vs * NROWS + r] = v;
                if ((unsigned)(tg[s] - v0) < (unsigned)VSPLIT) g_tlogit[r] = t;
            }
        }
        __syncthreads();   // partial writes / A reuse ordering before next task
    }
}

// ---------------- fused kernel ----------------
__global__ void __launch_bounds__(256, 1) __cluster_dims__(2, 1, 1)
fused_kernel(const int* __restrict__ inputs, const int* __restrict__ targets,
             const float* __restrict__ Wih, const float* __restrict__ bih,
             const float* __restrict__ Whh, const float* __restrict__ bhh,
             const float* __restrict__ bfc)
{
    extern __shared__ char smc[];
    if (blockIdx.x < NRNN)
        rnn_role(smc, inputs, Wih, bih, Whh, bhh);
    else
        worker_role(smc, targets, bfc);
}

// ============================================================
// Finalize: loss = mean_r [ log(sum_vs partial[vs][r]) - tlogit[r] ]
// ============================================================
__global__ void __launch_bounds__(1024, 1) finalize_kernel(float* __restrict__ out)
{
    __shared__ float red[1024];
    const int tid = threadIdx.x;
    float local = 0.f;
#pragma unroll
    for (int rr = 0; rr < 4; rr++) {
        int r = rr * 1024 + tid;
        float se = 0.f;
#pragma unroll
        for (int s = 0; s < NVS; s++)
            se += g_partials[s * NROWS + r];
        local += logf(se) - g_tlogit[r];
    }
    red[tid] = local;
    __syncthreads();
    for (int o = 512; o > 0; o >>= 1) {
        if (tid < o) red[tid] += red[tid + o];
        __syncthreads();
    }
    if (tid == 0) out[0] = red[0] * (1.0f / NROWS);
}

// ============================================================
// Launch
// ============================================================
extern "C" void kernel_launch(void* const* d_in, const int* in_sizes, int n_in,
                              void* d_out, int out_size)
{
    const int*   inputs  = (const int*)d_in[0];
    const int*   targets = (const int*)d_in[1];
    const float* Wih     = (const float*)d_in[2];
    const float* bih     = (const float*)d_in[3];
    const float* Whh     = (const float*)d_in[4];
    const float* bhh     = (const float*)d_in[5];
    const float* Wfc     = (const float*)d_in[6];
    const float* bfc     = (const float*)d_in[7];

    cudaFuncSetAttribute(fused_kernel, cudaFuncAttributeMaxDynamicSharedMemorySize, SM_TOT);

    convert_wfc_kernel<<<(VOCAB * HID / 4) / 256, 256>>>(Wfc);
    fused_kernel<<<GRID, 256, SM_TOT>>>(inputs, targets, Wih, bih, Whh, bhh, bfc);
    finalize_kernel<<<1, 1024>>>((float*)d_out);
}